// round 4
// baseline (speedup 1.0000x reference)
#include <cuda_runtime.h>
#include <math.h>

// Problem constants
#define NCLS 6
#define KPP 8
#define NPR 48
#define CDIM 128
#define HH 128
#define WW 128
#define BB 8
#define HORG 512

// Output layout (flattened tuple, fp32):
//   pred              (8,6,512,512)   ->  0          .. 12582912
//   prototype_expand  (8,48,128)      ->  12582912   .. 12632064
//   p2c_sim_map       (8,48,128,128)  ->  12632064   .. 18923520
//   distance_l2       (8,48,16384)    ->  18923520   .. 25214976
//   proto_new         (48,128)        ->  25214976   .. 25221120

// ---- device scratch (no allocation allowed) ----
__device__ unsigned char g_e[BB * HH * WW];        // effective class per lo-res pos
__device__ float g_centers[BB * 96 * CDIM];        // gelu(LN1(ctx))
__device__ int   g_nearest[BB * 96];
__device__ float g_proto[NPR * CDIM];              // proto_new
__device__ float g_pn2[NPR];                       // |proto_new|^2
__device__ float g_pred[BB * NCLS * HH * WW];      // pre-resize pred

__device__ __forceinline__ float gelu_exact(float x) {
    return 0.5f * x * (1.0f + erff(x * 0.70710678118654752440f));
}
__device__ __forceinline__ float warp_allreduce(float v) {
#pragma unroll
    for (int o = 16; o > 0; o >>= 1) v += __shfl_xor_sync(0xffffffffu, v, o);
    return v;
}

// ============================================================
// K0: e[b,h',w'] = (gt[b,4h',4w'] == 6) ? 0 : gt[b,4h',4w']
// gt dtype is ambiguous (jax silently makes int64 -> int32 unless x64
// is enabled). Detect per block: if gt is int64 with labels 0..6, every
// odd 32-bit word is the (zero) high half; if int32, odd words are
// random labels 0..6 and are ~never all zero over 128 samples.
// ============================================================
__global__ void k0_emap(const int* __restrict__ gt32) {
    __shared__ int s_nonzero;
    if (threadIdx.x == 0) s_nonzero = 0;
    __syncthreads();
    for (int t = threadIdx.x; t < 128; t += blockDim.x) {
        if (gt32[t * 16384 + 1] != 0) atomicOr(&s_nonzero, 1);
    }
    __syncthreads();
    int is64 = (s_nonzero == 0);

    int idx = blockIdx.x * blockDim.x + threadIdx.x;
    if (idx >= BB * HH * WW) return;
    int b = idx >> 14;
    int r = idx & 16383;
    int hp = r >> 7;
    int wp = r & 127;
    size_t elem = (size_t)b * 262144 + (size_t)hp * 2048 + (size_t)wp * 4;
    int lab = is64 ? gt32[2 * elem] : gt32[elem];   // low word == value (0..6)
    g_e[idx] = (lab == 6) ? (unsigned char)0 : (unsigned char)lab;
}

// ============================================================
// K1: per (b, patch): membership bits from the scrambled one_hot
//     reshape, masked feat sums, analytic softmax-context,
//     LN1 + GELU, nearest prototype (argmin over sqrt'd distances,
//     original protos). 128 blocks x 256 threads.
// ============================================================
__global__ void k1_centers(const float* __restrict__ feats,
                           const float* __restrict__ prototype,
                           const float* __restrict__ ln1g,
                           const float* __restrict__ ln1b) {
    __shared__ unsigned int mbits[6][32];   // [class][ph] bit=pw
    __shared__ int scnt[6];
    __shared__ float sS1[6][128];
    __shared__ float sStot[128];
    __shared__ float sproto[48 * 128];
    __shared__ float sp2[48];

    int bp = blockIdx.x;
    int b = bp >> 4;
    int p = bp & 15;
    int nh = p >> 2, nw = p & 3;
    int tid = threadIdx.x;
    int wid = tid >> 5, lane = tid & 31;

    if (tid < 6) scnt[tid] = 0;
    __syncthreads();

    // Phase A: membership of pred0[b,k,h,w] via the flat reshape of one_hot.
    // pred0 flat index n = k*16384 + h*128 + w maps to one_hot (h'=n/768,
    // w'=(n%768)/6, k'=n%6); value 1 iff k' == e[b,h',w'].
#pragma unroll 1
    for (int it = 0; it < 24; it++) {
        int idx = it * 256 + tid;                  // 0..6143 = k*1024 + pos
        int k = idx >> 10;
        int pos = idx & 1023;
        int ph = pos >> 5, pw = pos & 31;
        int n = k * 16384 + (nh * 32 + ph) * 128 + nw * 32 + pw;
        int hp = n / 768;
        int rem = n - hp * 768;
        int wp = rem / 6;
        int kq = rem - wp * 6;
        int m = (g_e[(b << 14) + (hp << 7) + wp] == (unsigned char)kq) ? 1 : 0;
        unsigned bal = __ballot_sync(0xffffffffu, m);
        if (lane == 0) {
            mbits[k][ph] = bal;
            atomicAdd(&scnt[k], __popc(bal));
        }
    }
    for (int idx = tid; idx < 6144; idx += 256) sproto[idx] = prototype[idx];
    __syncthreads();

    // |proto|^2 (original protos, for nearest)
    for (int j = wid; j < 48; j += 8) {
        float s = 0.f;
#pragma unroll
        for (int i = 0; i < 4; i++) {
            float v = sproto[j * 128 + lane + 32 * i];
            s += v * v;
        }
        s = warp_allreduce(s);
        if (lane == 0) sp2[j] = s;
    }

    // Phase B: masked sums over the 32x32 patch, warp per channel.
    for (int ci = 0; ci < 16; ci++) {
        int c = ci * 8 + wid;
        const float* fptr = feats + (((size_t)(b * 128 + c)) * 128 + nh * 32) * 128 + nw * 32 + lane;
        float at = 0, a0 = 0, a1 = 0, a2 = 0, a3 = 0, a4 = 0, a5 = 0;
#pragma unroll 4
        for (int ph = 0; ph < 32; ph++) {
            float f = fptr[ph * 128];
            at += f;
            if ((mbits[0][ph] >> lane) & 1) a0 += f;
            if ((mbits[1][ph] >> lane) & 1) a1 += f;
            if ((mbits[2][ph] >> lane) & 1) a2 += f;
            if ((mbits[3][ph] >> lane) & 1) a3 += f;
            if ((mbits[4][ph] >> lane) & 1) a4 += f;
            if ((mbits[5][ph] >> lane) & 1) a5 += f;
        }
        at = warp_allreduce(at);
        a0 = warp_allreduce(a0); a1 = warp_allreduce(a1); a2 = warp_allreduce(a2);
        a3 = warp_allreduce(a3); a4 = warp_allreduce(a4); a5 = warp_allreduce(a5);
        if (lane == 0) {
            sStot[c] = at;
            sS1[0][c] = a0; sS1[1][c] = a1; sS1[2][c] = a2;
            sS1[3][c] = a3; sS1[4][c] = a4; sS1[5][c] = a5;
        }
    }
    __syncthreads();

    // Phase C: analytic softmax-context, LN1+GELU, nearest proto. Warp per class.
    if (wid < 6) {
        int k = wid;
        const float W0 = 0.36787944117144232160f;  // exp(-1)
        int cnt = scnt[k];
        float denom = (float)cnt + W0 * (float)(1024 - cnt);
        float x[4];
#pragma unroll
        for (int i = 0; i < 4; i++) {
            int c = lane + 32 * i;
            x[i] = (W0 * sStot[c] + (1.0f - W0) * sS1[k][c]) / denom;
        }
        float s = warp_allreduce(x[0] + x[1] + x[2] + x[3]);
        float mu = s * (1.0f / 128.0f);
        float vs = 0;
#pragma unroll
        for (int i = 0; i < 4; i++) { float d = x[i] - mu; vs += d * d; }
        vs = warp_allreduce(vs);
        float inv = 1.0f / sqrtf(vs * (1.0f / 128.0f) + 1e-6f);
        float g[4];
        float c2p = 0;
#pragma unroll
        for (int i = 0; i < 4; i++) {
            int c = lane + 32 * i;
            float y = (x[i] - mu) * inv * ln1g[c] + ln1b[c];
            float gv = gelu_exact(y);
            g[i] = gv;
            c2p += gv * gv;
            g_centers[((size_t)(bp * 6 + k) << 7) + c] = gv;
        }
        float c2 = warp_allreduce(c2p);
        float best = 3.4e38f;
        int bj = 0;
        for (int j = 0; j < 48; j++) {
            float dp = 0;
#pragma unroll
            for (int i = 0; i < 4; i++) dp += g[i] * sproto[j * 128 + lane + 32 * i];
            float dot = warp_allreduce(dp);
            // match jax: argmin over sqrt(max(d2,0)) (sqrt collapses ties)
            float d = sqrtf(fmaxf(c2 + sp2[j] - 2.0f * dot, 0.0f));
            if (d < best) { best = d; bj = j; }
        }
        if (lane == 0) g_nearest[bp * 6 + k] = bj;
    }
}

// ============================================================
// K2: per-proto closed-form EMA of the sequential scan.
// 48 blocks x 128 threads.
// ============================================================
__global__ void k2_proto(const float* __restrict__ prototype,
                         float* __restrict__ out_pnew,
                         float* __restrict__ out_pexp) {
    int j = blockIdx.x;
    int tid = threadIdx.x;
    __shared__ int snear[768];
    __shared__ int tlist[768];
    __shared__ float ws[768];
    __shared__ int s_cnt;
    __shared__ float wsum[4];

    for (int t = tid; t < 768; t += 128) snear[t] = g_nearest[t];
    __syncthreads();
    if (tid == 0) {
        int c = 0;
        for (int t = 0; t < 768; t++)
            if (snear[t] == j) tlist[c++] = t;
        s_cnt = c;
    }
    __syncthreads();
    int cnt = s_cnt;
    for (int r = tid; r < cnt; r += 128)
        ws[r] = 0.001f * powf(0.999f, (float)(cnt - 1 - r));
    __syncthreads();

    int c = tid;
    float p0 = prototype[j * 128 + c];
    float acc = powf(0.999f, (float)cnt) * p0;
    for (int r = 0; r < cnt; r++)
        acc = fmaf(ws[r], g_centers[(size_t)tlist[r] * 128 + c], acc);
    float pnew = p0 + (acc - p0);   // match ref's prototype + sg(val - prototype)
    g_proto[j * 128 + c] = pnew;
    out_pnew[j * 128 + c] = pnew;
#pragma unroll
    for (int b = 0; b < 8; b++) out_pexp[b * 6144 + j * 128 + c] = pnew;

    float s = warp_allreduce(pnew * pnew);
    if ((tid & 31) == 0) wsum[tid >> 5] = s;
    __syncthreads();
    if (tid == 0) g_pn2[j] = wsum[0] + wsum[1] + wsum[2] + wsum[3];
}

// ============================================================
// K3: per (b, h-row): distances to all 48 protos, LN2 over protos,
//     GELU, per-class max over kp. 1024 blocks x 256 threads.
// ============================================================
__global__ void k3_dist(const float* __restrict__ feats,
                        const float* __restrict__ ln2g,
                        const float* __restrict__ ln2b,
                        float* __restrict__ out_p2c,
                        float* __restrict__ out_dist) {
    extern __shared__ float sm[];
    float* sf  = sm;           // [128 c][128 w]   = 16384
    float* spr = sm + 16384;   // [48][128]        =  6144
    float* sd  = sm + 22528;   // [48][128] dist   =  6144
    float* sp2 = sm + 28672;   // 48
    float* sg2 = sm + 28720;   // 48
    float* sb2 = sm + 28768;   // 48

    int h = blockIdx.x, b = blockIdx.y;
    int tid = threadIdx.x;
    size_t fb = ((size_t)b * 128) * 16384 + (size_t)h * 128;
    for (int idx = tid; idx < 16384; idx += 256) {
        int c = idx >> 7, w = idx & 127;
        sf[idx] = feats[fb + (size_t)c * 16384 + w];
    }
    for (int idx = tid; idx < 6144; idx += 256) spr[idx] = g_proto[idx];
    if (tid < 48) { sp2[tid] = g_pn2[tid]; sg2[tid] = ln2g[tid]; sb2[tid] = ln2b[tid]; }
    __syncthreads();

    int wid = tid >> 5, lane = tid & 31;
    int j0 = wid * 6;                    // 8 warps x 6 protos
    const float4* sf4 = (const float4*)sf;
    float4 acc[6];
#pragma unroll
    for (int jj = 0; jj < 6; jj++) acc[jj] = make_float4(0.f, 0.f, 0.f, 0.f);
    float4 f2a = make_float4(0.f, 0.f, 0.f, 0.f);

#pragma unroll 2
    for (int c = 0; c < 128; c++) {
        float4 f = sf4[c * 32 + lane];
        f2a.x = fmaf(f.x, f.x, f2a.x);
        f2a.y = fmaf(f.y, f.y, f2a.y);
        f2a.z = fmaf(f.z, f.z, f2a.z);
        f2a.w = fmaf(f.w, f.w, f2a.w);
#pragma unroll
        for (int jj = 0; jj < 6; jj++) {
            float pv = spr[(j0 + jj) * 128 + c];
            acc[jj].x = fmaf(pv, f.x, acc[jj].x);
            acc[jj].y = fmaf(pv, f.y, acc[jj].y);
            acc[jj].z = fmaf(pv, f.z, acc[jj].z);
            acc[jj].w = fmaf(pv, f.w, acc[jj].w);
        }
    }

    int w0 = lane * 4;
#pragma unroll
    for (int jj = 0; jj < 6; jj++) {
        int j = j0 + jj;
        float p2v = sp2[j];
        float4 d;
        d.x = sqrtf(fmaxf(f2a.x + p2v - 2.0f * acc[jj].x, 0.0f));
        d.y = sqrtf(fmaxf(f2a.y + p2v - 2.0f * acc[jj].y, 0.0f));
        d.z = sqrtf(fmaxf(f2a.z + p2v - 2.0f * acc[jj].z, 0.0f));
        d.w = sqrtf(fmaxf(f2a.w + p2v - 2.0f * acc[jj].w, 0.0f));
        ((float4*)sd)[j * 32 + lane] = d;
        size_t o = ((size_t)(b * 48 + j) << 14) + (size_t)(h * 128 + w0);
        *reinterpret_cast<float4*>(out_dist + o) = d;
    }
    __syncthreads();

    // LN over the 48 proto channels per position, GELU, class-max.
    if (tid < 128) {
        int w = tid;
        float x[48];
        float mu = 0;
#pragma unroll
        for (int j = 0; j < 48; j++) {
            float dd = sd[j * 128 + w];
            x[j] = 1.0f / (1.0f + 2.0f * dd);
            mu += x[j];
        }
        mu *= (1.0f / 48.0f);
        float vs = 0;
#pragma unroll
        for (int j = 0; j < 48; j++) { float d = x[j] - mu; vs += d * d; }
        float inv = 1.0f / sqrtf(vs * (1.0f / 48.0f) + 1e-6f);
        float mx0 = -3.4e38f, mx1 = -3.4e38f, mx2 = -3.4e38f,
              mx3 = -3.4e38f, mx4 = -3.4e38f, mx5 = -3.4e38f;
        size_t ob = ((size_t)(b * 48) << 14) + (size_t)(h * 128 + w);
#pragma unroll
        for (int j = 0; j < 48; j++) {
            float y = (x[j] - mu) * inv * sg2[j] + sb2[j];
            float gv = gelu_exact(y);
            out_p2c[ob + ((size_t)j << 14)] = gv;
            int nc = j % 6;  // compile-time in unrolled loop
            if (nc == 0) mx0 = fmaxf(mx0, gv);
            else if (nc == 1) mx1 = fmaxf(mx1, gv);
            else if (nc == 2) mx2 = fmaxf(mx2, gv);
            else if (nc == 3) mx3 = fmaxf(mx3, gv);
            else if (nc == 4) mx4 = fmaxf(mx4, gv);
            else mx5 = fmaxf(mx5, gv);
        }
        size_t pb = ((size_t)(b * 6) << 14) + (size_t)(h * 128 + w);
        g_pred[pb + (0 << 14)] = mx0;
        g_pred[pb + (1 << 14)] = mx1;
        g_pred[pb + (2 << 14)] = mx2;
        g_pred[pb + (3 << 14)] = mx3;
        g_pred[pb + (4 << 14)] = mx4;
        g_pred[pb + (5 << 14)] = mx5;
    }
}

// ============================================================
// K4: bilinear 128->512 (jax half-pixel centers; weight renorm at
// edges == clamp for linear kernel)
// ============================================================
__global__ void k4_resize(float* __restrict__ out_pred) {
    int idx = blockIdx.x * blockDim.x + threadIdx.x;  // exact grid: 12582912
    int ox = idx & 511;
    int oy = (idx >> 9) & 511;
    int ch = idx >> 18;  // b*6+nc, 0..47
    const float* src = g_pred + ((size_t)ch << 14);
    float sx = (ox + 0.5f) * 0.25f - 0.5f;
    float sy = (oy + 0.5f) * 0.25f - 0.5f;
    float x0f = floorf(sx), y0f = floorf(sy);
    float fx = sx - x0f, fy = sy - y0f;
    int x0 = (int)x0f, y0 = (int)y0f;
    int x0c = max(x0, 0), x1c = min(x0 + 1, 127);
    int y0c = max(y0, 0), y1c = min(y0 + 1, 127);
    float v00 = src[y0c * 128 + x0c], v01 = src[y0c * 128 + x1c];
    float v10 = src[y1c * 128 + x0c], v11 = src[y1c * 128 + x1c];
    float top = v00 + fx * (v01 - v00);
    float bot = v10 + fx * (v11 - v10);
    out_pred[idx] = top + fy * (bot - top);
}

extern "C" void kernel_launch(void* const* d_in, const int* in_sizes, int n_in,
                              void* d_out, int out_size) {
    const float* feats       = (const float*)d_in[0];
    const int*   gt32        = (const int*)d_in[1];   // int32 or int64 (detected)
    const float* prototype   = (const float*)d_in[2];
    const float* ln1g        = (const float*)d_in[3];
    const float* ln1b        = (const float*)d_in[4];
    const float* ln2g        = (const float*)d_in[5];
    const float* ln2b        = (const float*)d_in[6];

    float* out = (float*)d_out;
    float* out_pred = out;                    // 12582912
    float* out_pexp = out + 12582912;         // 49152
    float* out_p2c  = out + 12632064;         // 6291456
    float* out_dist = out + 18923520;         // 6291456
    float* out_pnew = out + 25214976;         // 6144

    cudaFuncSetAttribute(k3_dist, cudaFuncAttributeMaxDynamicSharedMemorySize, 28816 * 4);

    k0_emap<<<512, 256>>>(gt32);
    k1_centers<<<128, 256>>>(feats, prototype, ln1g, ln1b);
    k2_proto<<<48, 128>>>(prototype, out_pnew, out_pexp);
    dim3 g3(128, 8);
    k3_dist<<<g3, 256, 28816 * 4>>>(feats, ln2g, ln2b, out_p2c, out_dist);
    k4_resize<<<49152, 256>>>(out_pred);
}

// round 5
// speedup vs baseline: 1.3706x; 1.3706x over previous
#include <cuda_runtime.h>
#include <math.h>

// Problem constants
#define NCLS 6
#define KPP 8
#define NPR 48
#define CDIM 128
#define HH 128
#define WW 128
#define BB 8
#define HORG 512

typedef unsigned long long ull;

// Output layout (flattened tuple, fp32):
//   pred              (8,6,512,512)   ->  0          .. 12582912
//   prototype_expand  (8,48,128)      ->  12582912   .. 12632064
//   p2c_sim_map       (8,48,128,128)  ->  12632064   .. 18923520
//   distance_l2       (8,48,16384)    ->  18923520   .. 25214976
//   proto_new         (48,128)        ->  25214976   .. 25221120

// ---- device scratch (no allocation allowed) ----
__device__ unsigned char g_e[BB * HH * WW];        // effective class per lo-res pos
__device__ float g_centers[BB * 96 * CDIM];        // gelu(LN1(ctx))
__device__ int   g_nearest[BB * 96];
__device__ float g_proto[NPR * CDIM];              // proto_new
__device__ float g_pn2[NPR];                       // |proto_new|^2
__device__ float g_pred[BB * NCLS * HH * WW];      // pre-resize pred
__device__ float g_Stot[128 * 128];                // [bp][c] total feat sums
__device__ float g_S1[6 * 128 * 128];              // [k][bp][c] masked sums
__device__ int   g_cnt[128 * 6];                   // [bp][k] member counts

__device__ __forceinline__ float gelu_exact(float x) {
    return 0.5f * x * (1.0f + erff(x * 0.70710678118654752440f));
}
__device__ __forceinline__ float warp_allreduce(float v) {
#pragma unroll
    for (int o = 16; o > 0; o >>= 1) v += __shfl_xor_sync(0xffffffffu, v, o);
    return v;
}
__device__ __forceinline__ ull pack2(float lo, float hi) {
    ull r;
    asm("mov.b64 %0, {%1, %2};" : "=l"(r) : "f"(lo), "f"(hi));
    return r;
}
__device__ __forceinline__ float2 unpk2(ull v) {
    float2 r;
    asm("mov.b64 {%0, %1}, %2;" : "=f"(r.x), "=f"(r.y) : "l"(v));
    return r;
}
__device__ __forceinline__ ull ffma2(ull a, ull b, ull c) {
    ull d;
    asm("fma.rn.f32x2 %0, %1, %2, %3;" : "=l"(d) : "l"(a), "l"(b), "l"(c));
    return d;
}

// ============================================================
// K0: e[b,h',w'] = (gt[b,4h',4w'] == 6) ? 0 : gt[b,4h',4w']
// gt dtype detection (int64 with labels 0..6 -> every odd 32-bit word 0).
// ============================================================
__global__ void k0_emap(const int* __restrict__ gt32) {
    __shared__ int s_nonzero;
    if (threadIdx.x == 0) s_nonzero = 0;
    __syncthreads();
    for (int t = threadIdx.x; t < 128; t += blockDim.x) {
        if (gt32[t * 16384 + 1] != 0) atomicOr(&s_nonzero, 1);
    }
    __syncthreads();
    int is64 = (s_nonzero == 0);

    int idx = blockIdx.x * blockDim.x + threadIdx.x;
    if (idx >= BB * HH * WW) return;
    int b = idx >> 14;
    int r = idx & 16383;
    int hp = r >> 7;
    int wp = r & 127;
    size_t elem = (size_t)b * 262144 + (size_t)hp * 2048 + (size_t)wp * 4;
    int lab = is64 ? gt32[2 * elem] : gt32[elem];
    g_e[idx] = (lab == 6) ? (unsigned char)0 : (unsigned char)lab;
}

// ============================================================
// K1b: per (b,patch,channel-group): membership bits + masked feat
// sums. grid (128 patches, 4 groups) x 256 threads.
// ============================================================
__global__ void k1b_sums(const float* __restrict__ feats) {
    __shared__ unsigned int mbits[6][32];
    __shared__ int scnt[6];

    int bp = blockIdx.x;
    int g = blockIdx.y;
    int b = bp >> 4;
    int p = bp & 15;
    int nh = p >> 2, nw = p & 3;
    int tid = threadIdx.x;
    int wid = tid >> 5, lane = tid & 31;

    if (tid < 6) scnt[tid] = 0;
    __syncthreads();

    // Phase A: membership of pred0[b,k,h,w] via flat one_hot reshape.
#pragma unroll 1
    for (int it = 0; it < 24; it++) {
        int idx = it * 256 + tid;                  // k*1024 + pos
        int k = idx >> 10;
        int pos = idx & 1023;
        int ph = pos >> 5, pw = pos & 31;
        int n = k * 16384 + (nh * 32 + ph) * 128 + nw * 32 + pw;
        int hp = n / 768;
        int rem = n - hp * 768;
        int wp = rem / 6;
        int kq = rem - wp * 6;
        int m = (g_e[(b << 14) + (hp << 7) + wp] == (unsigned char)kq) ? 1 : 0;
        unsigned bal = __ballot_sync(0xffffffffu, m);
        if (lane == 0) {
            mbits[k][ph] = bal;
            atomicAdd(&scnt[k], __popc(bal));
        }
    }
    __syncthreads();
    if (g == 0 && tid < 6) g_cnt[bp * 6 + tid] = scnt[tid];

    // Phase B: masked sums over the 32x32 patch; warp per channel, 4 per warp.
    for (int ci = 0; ci < 4; ci++) {
        int c = g * 32 + ci * 8 + wid;
        const float* fptr = feats + (((size_t)(b * 128 + c)) * 128 + nh * 32) * 128 + nw * 32 + lane;
        float at = 0, a0 = 0, a1 = 0, a2 = 0, a3 = 0, a4 = 0, a5 = 0;
#pragma unroll 8
        for (int ph = 0; ph < 32; ph++) {
            float f = fptr[ph * 128];
            at += f;
            if ((mbits[0][ph] >> lane) & 1) a0 += f;
            if ((mbits[1][ph] >> lane) & 1) a1 += f;
            if ((mbits[2][ph] >> lane) & 1) a2 += f;
            if ((mbits[3][ph] >> lane) & 1) a3 += f;
            if ((mbits[4][ph] >> lane) & 1) a4 += f;
            if ((mbits[5][ph] >> lane) & 1) a5 += f;
        }
        at = warp_allreduce(at);
        a0 = warp_allreduce(a0); a1 = warp_allreduce(a1); a2 = warp_allreduce(a2);
        a3 = warp_allreduce(a3); a4 = warp_allreduce(a4); a5 = warp_allreduce(a5);
        if (lane == 0) {
            g_Stot[bp * 128 + c] = at;
            g_S1[0 * 16384 + bp * 128 + c] = a0;
            g_S1[1 * 16384 + bp * 128 + c] = a1;
            g_S1[2 * 16384 + bp * 128 + c] = a2;
            g_S1[3 * 16384 + bp * 128 + c] = a3;
            g_S1[4 * 16384 + bp * 128 + c] = a4;
            g_S1[5 * 16384 + bp * 128 + c] = a5;
        }
    }
}

// ============================================================
// K1c: analytic softmax-context, LN1+GELU, nearest prototype.
// 128 blocks x 192 threads (warp per class).
// ============================================================
__global__ void k1c_centers(const float* __restrict__ prototype,
                            const float* __restrict__ ln1g,
                            const float* __restrict__ ln1b) {
    __shared__ float sproto[48 * 128];
    __shared__ float sp2[48];

    int bp = blockIdx.x;
    int tid = threadIdx.x;
    int wid = tid >> 5, lane = tid & 31;  // wid = class k (0..5)

    for (int idx = tid; idx < 6144; idx += 192) sproto[idx] = prototype[idx];
    __syncthreads();

    for (int j = wid; j < 48; j += 6) {
        float s = 0.f;
#pragma unroll
        for (int i = 0; i < 4; i++) {
            float v = sproto[j * 128 + lane + 32 * i];
            s += v * v;
        }
        s = warp_allreduce(s);
        if (lane == 0) sp2[j] = s;
    }
    __syncthreads();

    int k = wid;
    const float W0 = 0.36787944117144232160f;  // exp(-1)
    int cnt = g_cnt[bp * 6 + k];
    float denom = (float)cnt + W0 * (float)(1024 - cnt);
    float x[4];
#pragma unroll
    for (int i = 0; i < 4; i++) {
        int c = lane + 32 * i;
        float st = g_Stot[bp * 128 + c];
        float s1 = g_S1[k * 16384 + bp * 128 + c];
        x[i] = (W0 * st + (1.0f - W0) * s1) / denom;
    }
    float s = warp_allreduce(x[0] + x[1] + x[2] + x[3]);
    float mu = s * (1.0f / 128.0f);
    float vs = 0;
#pragma unroll
    for (int i = 0; i < 4; i++) { float d = x[i] - mu; vs += d * d; }
    vs = warp_allreduce(vs);
    float inv = 1.0f / sqrtf(vs * (1.0f / 128.0f) + 1e-6f);
    float g[4];
    float c2p = 0;
#pragma unroll
    for (int i = 0; i < 4; i++) {
        int c = lane + 32 * i;
        float y = (x[i] - mu) * inv * ln1g[c] + ln1b[c];
        float gv = gelu_exact(y);
        g[i] = gv;
        c2p += gv * gv;
        g_centers[((size_t)(bp * 6 + k) << 7) + c] = gv;
    }
    float c2 = warp_allreduce(c2p);
    float best = 3.4e38f;
    int bj = 0;
    for (int j = 0; j < 48; j++) {
        float dp = 0;
#pragma unroll
        for (int i = 0; i < 4; i++) dp += g[i] * sproto[j * 128 + lane + 32 * i];
        float dot = warp_allreduce(dp);
        float d = sqrtf(fmaxf(c2 + sp2[j] - 2.0f * dot, 0.0f));
        if (d < best) { best = d; bj = j; }
    }
    if (lane == 0) g_nearest[bp * 6 + k] = bj;
}

// ============================================================
// K2: per-proto closed-form EMA. 48 blocks x 128 threads.
// ============================================================
__global__ void k2_proto(const float* __restrict__ prototype,
                         float* __restrict__ out_pnew,
                         float* __restrict__ out_pexp) {
    int j = blockIdx.x;
    int tid = threadIdx.x;
    __shared__ int snear[768];
    __shared__ int tlist[768];
    __shared__ float ws[768];
    __shared__ int s_cnt;
    __shared__ float wsum[4];

    const float L999 = -0.00144349540456856f;  // log2(0.999)

    for (int t = tid; t < 768; t += 128) snear[t] = g_nearest[t];
    __syncthreads();
    if (tid == 0) {
        int c = 0;
        for (int t = 0; t < 768; t++)
            if (snear[t] == j) tlist[c++] = t;
        s_cnt = c;
    }
    __syncthreads();
    int cnt = s_cnt;
    for (int r = tid; r < cnt; r += 128)
        ws[r] = 0.001f * exp2f((float)(cnt - 1 - r) * L999);
    __syncthreads();

    int c = tid;
    float p0 = prototype[j * 128 + c];
    float acc = exp2f((float)cnt * L999) * p0;
    for (int r = 0; r < cnt; r++)
        acc = fmaf(ws[r], g_centers[(size_t)tlist[r] * 128 + c], acc);
    float pnew = p0 + (acc - p0);
    g_proto[j * 128 + c] = pnew;
    out_pnew[j * 128 + c] = pnew;
#pragma unroll
    for (int b = 0; b < 8; b++) out_pexp[b * 6144 + j * 128 + c] = pnew;

    float s = warp_allreduce(pnew * pnew);
    if ((tid & 31) == 0) wsum[tid >> 5] = s;
    __syncthreads();
    if (tid == 0) g_pn2[j] = wsum[0] + wsum[1] + wsum[2] + wsum[3];
}

// ============================================================
// K3: per (b,h-row): distances to 48 protos (f32x2-packed FMA,
// feats straight from L1), LN2 over protos, GELU, class max.
// grid (128,8) x 256 threads; smem ~73KB -> 3 blocks/SM.
// ============================================================
__global__ void __launch_bounds__(256, 3)
k3_dist(const float* __restrict__ feats,
        const float* __restrict__ ln2g,
        const float* __restrict__ ln2b,
        float* __restrict__ out_p2c,
        float* __restrict__ out_dist) {
    extern __shared__ float sm[];
    ull*   spr2 = (ull*)sm;          // [48][128] duplicated (p,p) = 48KB
    float* sd   = sm + 12288;        // [48][128] x = 1/(1+2d)     = 24KB
    float* sp2  = sm + 18432;        // 48
    float* sg2  = sm + 18480;        // 48
    float* sb2  = sm + 18528;        // 48

    int h = blockIdx.x, b = blockIdx.y;
    int tid = threadIdx.x;
    int wid = tid >> 5, lane = tid & 31;

    for (int idx = tid; idx < 6144; idx += 256) {
        float p = g_proto[idx];
        spr2[idx] = pack2(p, p);
    }
    if (tid < 48) { sp2[tid] = g_pn2[tid]; sg2[tid] = ln2g[tid]; sb2[tid] = ln2b[tid]; }
    __syncthreads();

    int j0 = wid * 6;                              // 8 warps x 6 protos
    const float4* fp = (const float4*)(feats + ((size_t)b * 128) * 16384 + (size_t)h * 128) + lane;
    // c stride in float4 units: 16384/4 = 4096

    ull accA[6], accB[6];
#pragma unroll
    for (int jj = 0; jj < 6; jj++) { accA[jj] = 0ull; accB[jj] = 0ull; }
    ull f2xy = 0ull, f2zw = 0ull;

#pragma unroll 4
    for (int c = 0; c < 128; c++) {
        float4 f = fp[(size_t)c * 4096];
        ull fxy = pack2(f.x, f.y);
        ull fzw = pack2(f.z, f.w);
        f2xy = ffma2(fxy, fxy, f2xy);
        f2zw = ffma2(fzw, fzw, f2zw);
#pragma unroll
        for (int jj = 0; jj < 6; jj++) {
            ull pv = spr2[(j0 + jj) * 128 + c];
            accA[jj] = ffma2(pv, fxy, accA[jj]);
            accB[jj] = ffma2(pv, fzw, accB[jj]);
        }
    }

    float2 f2a = unpk2(f2xy), f2b = unpk2(f2zw);
    int w0 = lane * 4;
#pragma unroll
    for (int jj = 0; jj < 6; jj++) {
        int j = j0 + jj;
        float p2v = sp2[j];
        float2 da = unpk2(accA[jj]), db = unpk2(accB[jj]);
        float4 d;
        d.x = sqrtf(fmaxf(f2a.x + p2v - 2.0f * da.x, 0.0f));
        d.y = sqrtf(fmaxf(f2a.y + p2v - 2.0f * da.y, 0.0f));
        d.z = sqrtf(fmaxf(f2b.x + p2v - 2.0f * db.x, 0.0f));
        d.w = sqrtf(fmaxf(f2b.y + p2v - 2.0f * db.y, 0.0f));
        size_t o = ((size_t)(b * 48 + j) << 14) + (size_t)(h * 128 + w0);
        *reinterpret_cast<float4*>(out_dist + o) = d;
        float4 xv;
        xv.x = 1.0f / (1.0f + 2.0f * d.x);
        xv.y = 1.0f / (1.0f + 2.0f * d.y);
        xv.z = 1.0f / (1.0f + 2.0f * d.z);
        xv.w = 1.0f / (1.0f + 2.0f * d.w);
        ((float4*)sd)[j * 32 + lane] = xv;
    }
    __syncthreads();

    // LN over 48 proto channels per position, GELU, class max.
    // All 256 threads: pair (even,odd lanes) splits j in halves of 24.
    {
        int w = tid >> 1;
        int half = tid & 1;
        int jb = half * 24;
        float xv[24];
        float s = 0;
#pragma unroll
        for (int t = 0; t < 24; t++) {
            xv[t] = sd[(jb + t) * 128 + w];
            s += xv[t];
        }
        s += __shfl_xor_sync(0xffffffffu, s, 1);
        float mu = s * (1.0f / 48.0f);
        float vs = 0;
#pragma unroll
        for (int t = 0; t < 24; t++) { float d = xv[t] - mu; vs += d * d; }
        vs += __shfl_xor_sync(0xffffffffu, vs, 1);
        float inv = 1.0f / sqrtf(vs * (1.0f / 48.0f) + 1e-6f);

        float mx[6];
#pragma unroll
        for (int ncc = 0; ncc < 6; ncc++) mx[ncc] = -3.4e38f;
        size_t ob = ((size_t)(b * 48) << 14) + (size_t)(h * 128 + w);
#pragma unroll
        for (int t = 0; t < 24; t++) {
            int j = jb + t;
            float y = (xv[t] - mu) * inv * sg2[j] + sb2[j];
            float gv = gelu_exact(y);
            out_p2c[ob + ((size_t)j << 14)] = gv;
            int ncc = t % 6;  // (jb+t)%6 == t%6 since jb is 0 or 24
            mx[ncc] = fmaxf(mx[ncc], gv);
        }
#pragma unroll
        for (int ncc = 0; ncc < 6; ncc++)
            mx[ncc] = fmaxf(mx[ncc], __shfl_xor_sync(0xffffffffu, mx[ncc], 1));
        if (half == 0) {
            size_t pb = ((size_t)(b * 6) << 14) + (size_t)(h * 128 + w);
#pragma unroll
            for (int ncc = 0; ncc < 6; ncc++)
                g_pred[pb + ((size_t)ncc << 14)] = mx[ncc];
        }
    }
}

// ============================================================
// K4: bilinear 128->512 (jax half-pixel centers, edge clamp)
// ============================================================
__global__ void k4_resize(float* __restrict__ out_pred) {
    int idx = blockIdx.x * blockDim.x + threadIdx.x;
    int ox = idx & 511;
    int oy = (idx >> 9) & 511;
    int ch = idx >> 18;
    const float* src = g_pred + ((size_t)ch << 14);
    float sx = (ox + 0.5f) * 0.25f - 0.5f;
    float sy = (oy + 0.5f) * 0.25f - 0.5f;
    float x0f = floorf(sx), y0f = floorf(sy);
    float fx = sx - x0f, fy = sy - y0f;
    int x0 = (int)x0f, y0 = (int)y0f;
    int x0c = max(x0, 0), x1c = min(x0 + 1, 127);
    int y0c = max(y0, 0), y1c = min(y0 + 1, 127);
    float v00 = src[y0c * 128 + x0c], v01 = src[y0c * 128 + x1c];
    float v10 = src[y1c * 128 + x0c], v11 = src[y1c * 128 + x1c];
    float top = v00 + fx * (v01 - v00);
    float bot = v10 + fx * (v11 - v10);
    out_pred[idx] = top + fy * (bot - top);
}

extern "C" void kernel_launch(void* const* d_in, const int* in_sizes, int n_in,
                              void* d_out, int out_size) {
    const float* feats       = (const float*)d_in[0];
    const int*   gt32        = (const int*)d_in[1];
    const float* prototype   = (const float*)d_in[2];
    const float* ln1g        = (const float*)d_in[3];
    const float* ln1b        = (const float*)d_in[4];
    const float* ln2g        = (const float*)d_in[5];
    const float* ln2b        = (const float*)d_in[6];

    float* out = (float*)d_out;
    float* out_pred = out;                    // 12582912
    float* out_pexp = out + 12582912;         // 49152
    float* out_p2c  = out + 12632064;         // 6291456
    float* out_dist = out + 18923520;         // 6291456
    float* out_pnew = out + 25214976;         // 6144

    static int smem_set = 0;
    if (!smem_set) {
        cudaFuncSetAttribute(k3_dist, cudaFuncAttributeMaxDynamicSharedMemorySize, 18576 * 4);
        smem_set = 1;
    }

    k0_emap<<<512, 256>>>(gt32);
    dim3 g1(128, 4);
    k1b_sums<<<g1, 256>>>(feats);
    k1c_centers<<<128, 192>>>(prototype, ln1g, ln1b);
    k2_proto<<<48, 128>>>(prototype, out_pnew, out_pexp);
    dim3 g3(128, 8);
    k3_dist<<<g3, 256, 18576 * 4>>>(feats, ln2g, ln2b, out_p2c, out_dist);
    k4_resize<<<49152, 256>>>(out_pred);
}

// round 10
// speedup vs baseline: 1.5116x; 1.1029x over previous
#include <cuda_runtime.h>
#include <math.h>

// Problem constants
#define NCLS 6
#define KPP 8
#define NPR 48
#define CDIM 128
#define HH 128
#define WW 128
#define BB 8
#define HORG 512

typedef unsigned long long ull;

// Output layout (flattened tuple, fp32):
//   pred              (8,6,512,512)   ->  0          .. 12582912
//   prototype_expand  (8,48,128)      ->  12582912   .. 12632064
//   p2c_sim_map       (8,48,128,128)  ->  12632064   .. 18923520
//   distance_l2       (8,48,16384)    ->  18923520   .. 25214976
//   proto_new         (48,128)        ->  25214976   .. 25221120

// ---- device scratch (no allocation allowed) ----
__device__ unsigned char g_e[BB * HH * WW];
__device__ float g_centers[BB * 96 * CDIM];
__device__ int   g_nearest[BB * 96];
__device__ float g_proto[NPR * CDIM];
__device__ float g_pn2[NPR];
__device__ float g_pred[BB * NCLS * HH * WW];
__device__ float g_Stot[128 * 128];
__device__ float g_S1[6 * 128 * 128];
__device__ int   g_cnt[128 * 6];

__device__ __forceinline__ float gelu_exact(float x) {
    return 0.5f * x * (1.0f + erff(x * 0.70710678118654752440f));
}
__device__ __forceinline__ float warp_allreduce(float v) {
#pragma unroll
    for (int o = 16; o > 0; o >>= 1) v += __shfl_xor_sync(0xffffffffu, v, o);
    return v;
}
__device__ __forceinline__ ull pack2(float lo, float hi) {
    ull r;
    asm("mov.b64 %0, {%1, %2};" : "=l"(r) : "f"(lo), "f"(hi));
    return r;
}
__device__ __forceinline__ float2 unpk2(ull v) {
    float2 r;
    asm("mov.b64 {%0, %1}, %2;" : "=f"(r.x), "=f"(r.y) : "l"(v));
    return r;
}
__device__ __forceinline__ ull ffma2(ull a, ull b, ull c) {
    ull d;
    asm("fma.rn.f32x2 %0, %1, %2, %3;" : "=l"(d) : "l"(a), "l"(b), "l"(c));
    return d;
}

// ============================================================
// K0: downsampled label map with dtype autodetect (int64 vs int32).
// ============================================================
__global__ void k0_emap(const int* __restrict__ gt32) {
    __shared__ int s_nonzero;
    if (threadIdx.x == 0) s_nonzero = 0;
    __syncthreads();
    for (int t = threadIdx.x; t < 128; t += blockDim.x) {
        if (gt32[t * 16384 + 1] != 0) atomicOr(&s_nonzero, 1);
    }
    __syncthreads();
    int is64 = (s_nonzero == 0);

    int idx = blockIdx.x * blockDim.x + threadIdx.x;
    if (idx >= BB * HH * WW) return;
    int b = idx >> 14;
    int r = idx & 16383;
    int hp = r >> 7;
    int wp = r & 127;
    size_t elem = (size_t)b * 262144 + (size_t)hp * 2048 + (size_t)wp * 4;
    int lab = is64 ? gt32[2 * elem] : gt32[elem];
    g_e[idx] = (lab == 6) ? (unsigned char)0 : (unsigned char)lab;
}

// ============================================================
// K1b: per (b,patch,channel-group): membership bits + masked sums.
// grid (128,4) x 256 threads.
// ============================================================
__global__ void k1b_sums(const float* __restrict__ feats) {
    __shared__ unsigned int mbits[6][32];
    __shared__ int scnt[6];

    int bp = blockIdx.x;
    int g = blockIdx.y;
    int b = bp >> 4;
    int p = bp & 15;
    int nh = p >> 2, nw = p & 3;
    int tid = threadIdx.x;
    int wid = tid >> 5, lane = tid & 31;

    if (tid < 6) scnt[tid] = 0;
    __syncthreads();

#pragma unroll 1
    for (int it = 0; it < 24; it++) {
        int idx = it * 256 + tid;
        int k = idx >> 10;
        int pos = idx & 1023;
        int ph = pos >> 5, pw = pos & 31;
        int n = k * 16384 + (nh * 32 + ph) * 128 + nw * 32 + pw;
        int hp = n / 768;
        int rem = n - hp * 768;
        int wp = rem / 6;
        int kq = rem - wp * 6;
        int m = (g_e[(b << 14) + (hp << 7) + wp] == (unsigned char)kq) ? 1 : 0;
        unsigned bal = __ballot_sync(0xffffffffu, m);
        if (lane == 0) {
            mbits[k][ph] = bal;
            atomicAdd(&scnt[k], __popc(bal));
        }
    }
    __syncthreads();
    if (g == 0 && tid < 6) g_cnt[bp * 6 + tid] = scnt[tid];

    for (int ci = 0; ci < 4; ci++) {
        int c = g * 32 + ci * 8 + wid;
        const float* fptr = feats + (((size_t)(b * 128 + c)) * 128 + nh * 32) * 128 + nw * 32 + lane;
        float at = 0, a0 = 0, a1 = 0, a2 = 0, a3 = 0, a4 = 0, a5 = 0;
#pragma unroll 8
        for (int ph = 0; ph < 32; ph++) {
            float f = fptr[ph * 128];
            at += f;
            if ((mbits[0][ph] >> lane) & 1) a0 += f;
            if ((mbits[1][ph] >> lane) & 1) a1 += f;
            if ((mbits[2][ph] >> lane) & 1) a2 += f;
            if ((mbits[3][ph] >> lane) & 1) a3 += f;
            if ((mbits[4][ph] >> lane) & 1) a4 += f;
            if ((mbits[5][ph] >> lane) & 1) a5 += f;
        }
        at = warp_allreduce(at);
        a0 = warp_allreduce(a0); a1 = warp_allreduce(a1); a2 = warp_allreduce(a2);
        a3 = warp_allreduce(a3); a4 = warp_allreduce(a4); a5 = warp_allreduce(a5);
        if (lane == 0) {
            g_Stot[bp * 128 + c] = at;
            g_S1[0 * 16384 + bp * 128 + c] = a0;
            g_S1[1 * 16384 + bp * 128 + c] = a1;
            g_S1[2 * 16384 + bp * 128 + c] = a2;
            g_S1[3 * 16384 + bp * 128 + c] = a3;
            g_S1[4 * 16384 + bp * 128 + c] = a4;
            g_S1[5 * 16384 + bp * 128 + c] = a5;
        }
    }
}

// ============================================================
// K1c: analytic softmax-context, LN1+GELU, nearest prototype.
// 128 blocks x 192 threads (warp per class).
// ============================================================
__global__ void k1c_centers(const float* __restrict__ prototype,
                            const float* __restrict__ ln1g,
                            const float* __restrict__ ln1b) {
    __shared__ float sproto[48 * 128];
    __shared__ float sp2[48];

    int bp = blockIdx.x;
    int tid = threadIdx.x;
    int wid = tid >> 5, lane = tid & 31;

    for (int idx = tid; idx < 6144; idx += 192) sproto[idx] = prototype[idx];
    __syncthreads();

    for (int j = wid; j < 48; j += 6) {
        float s = 0.f;
#pragma unroll
        for (int i = 0; i < 4; i++) {
            float v = sproto[j * 128 + lane + 32 * i];
            s += v * v;
        }
        s = warp_allreduce(s);
        if (lane == 0) sp2[j] = s;
    }
    __syncthreads();

    int k = wid;
    const float W0 = 0.36787944117144232160f;
    int cnt = g_cnt[bp * 6 + k];
    float denom = (float)cnt + W0 * (float)(1024 - cnt);
    float x[4];
#pragma unroll
    for (int i = 0; i < 4; i++) {
        int c = lane + 32 * i;
        float st = g_Stot[bp * 128 + c];
        float s1 = g_S1[k * 16384 + bp * 128 + c];
        x[i] = (W0 * st + (1.0f - W0) * s1) / denom;
    }
    float s = warp_allreduce(x[0] + x[1] + x[2] + x[3]);
    float mu = s * (1.0f / 128.0f);
    float vs = 0;
#pragma unroll
    for (int i = 0; i < 4; i++) { float d = x[i] - mu; vs += d * d; }
    vs = warp_allreduce(vs);
    float inv = 1.0f / sqrtf(vs * (1.0f / 128.0f) + 1e-6f);
    float g[4];
    float c2p = 0;
#pragma unroll
    for (int i = 0; i < 4; i++) {
        int c = lane + 32 * i;
        float y = (x[i] - mu) * inv * ln1g[c] + ln1b[c];
        float gv = gelu_exact(y);
        g[i] = gv;
        c2p += gv * gv;
        g_centers[((size_t)(bp * 6 + k) << 7) + c] = gv;
    }
    float c2 = warp_allreduce(c2p);
    float best = 3.4e38f;
    int bj = 0;
    for (int j = 0; j < 48; j++) {
        float dp = 0;
#pragma unroll
        for (int i = 0; i < 4; i++) dp += g[i] * sproto[j * 128 + lane + 32 * i];
        float dot = warp_allreduce(dp);
        float d = sqrtf(fmaxf(c2 + sp2[j] - 2.0f * dot, 0.0f));
        if (d < best) { best = d; bj = j; }
    }
    if (lane == 0) g_nearest[bp * 6 + k] = bj;
}

// ============================================================
// K2: per-proto closed-form EMA -- latency-tolerant.
// 48 blocks x 512 threads (4 r-groups x 128 channels).
// ============================================================
__global__ void k2_proto(const float* __restrict__ prototype,
                         float* __restrict__ out_pnew,
                         float* __restrict__ out_pexp) {
    int j = blockIdx.x;
    int tid = threadIdx.x;
    int c = tid & 127;
    int grp = tid >> 7;                 // 0..3
    __shared__ int tlist[768];
    __shared__ float ws[768];
    __shared__ int s_cnt;
    __shared__ float partial[3][128];
    __shared__ float wsum[4];

    const float L999 = -0.00144349540456856f;   // log2(0.999)

    // warp 0: ballot-based parallel build of tlist
    if (tid < 32) {
        int c0 = 0;
        unsigned lt = (1u << tid) - 1u;
#pragma unroll 1
        for (int it = 0; it < 24; it++) {
            int t = it * 32 + tid;
            int m = (g_nearest[t] == j) ? 1 : 0;
            unsigned bal = __ballot_sync(0xffffffffu, m);
            if (m) tlist[c0 + __popc(bal & lt)] = t;
            c0 += __popc(bal);
        }
        if (tid == 0) s_cnt = c0;
    }
    __syncthreads();
    int cnt = s_cnt;
    for (int r = tid; r < cnt; r += 512)
        ws[r] = 0.001f * exp2f((float)(cnt - 1 - r) * L999);
    __syncthreads();

    // weighted sum: group g takes r = g, g+4, g+8 ... with 2 accumulators
    float a0 = 0.f, a1 = 0.f;
    int r = grp;
    for (; r + 4 < cnt; r += 8) {
        a0 = fmaf(ws[r],     __ldcs(&g_centers[(size_t)tlist[r]     * 128 + c]), a0);
        a1 = fmaf(ws[r + 4], __ldcs(&g_centers[(size_t)tlist[r + 4] * 128 + c]), a1);
    }
    if (r < cnt)
        a0 = fmaf(ws[r], __ldcs(&g_centers[(size_t)tlist[r] * 128 + c]), a0);
    float acc = a0 + a1;

    if (grp > 0) partial[grp - 1][c] = acc;
    __syncthreads();

    if (grp == 0) {
        float p0 = prototype[j * 128 + c];
        acc += partial[0][c] + partial[1][c] + partial[2][c];
        acc += exp2f((float)cnt * L999) * p0;
        float pnew = p0 + (acc - p0);
        g_proto[j * 128 + c] = pnew;
        out_pnew[j * 128 + c] = pnew;
#pragma unroll
        for (int b = 0; b < 8; b++) out_pexp[b * 6144 + j * 128 + c] = pnew;

        float s = warp_allreduce(pnew * pnew);
        if ((tid & 31) == 0) wsum[tid >> 5] = s;
    }
    __syncthreads();
    if (tid == 0) g_pn2[j] = wsum[0] + wsum[1] + wsum[2] + wsum[3];
}

// ============================================================
// K3: distances to 48 protos (f32x2 FMA), LN2, GELU, class max.
// grid (128,8) x 256 threads; smem ~73KB -> 3 blocks/SM.
// ============================================================
__global__ void __launch_bounds__(256, 3)
k3_dist(const float* __restrict__ feats,
        const float* __restrict__ ln2g,
        const float* __restrict__ ln2b,
        float* __restrict__ out_p2c,
        float* __restrict__ out_dist) {
    extern __shared__ float sm[];
    ull*   spr2 = (ull*)sm;          // [48][128] duplicated (p,p)
    float* sd   = sm + 12288;        // [48][128] x = 1/(1+2d)
    float* sp2  = sm + 18432;
    float* sg2  = sm + 18480;
    float* sb2  = sm + 18528;

    int h = blockIdx.x, b = blockIdx.y;
    int tid = threadIdx.x;
    int wid = tid >> 5, lane = tid & 31;

    for (int idx = tid; idx < 6144; idx += 256) {
        float p = g_proto[idx];
        spr2[idx] = pack2(p, p);
    }
    if (tid < 48) { sp2[tid] = g_pn2[tid]; sg2[tid] = ln2g[tid]; sb2[tid] = ln2b[tid]; }
    __syncthreads();

    int j0 = wid * 6;
    const float4* fp = (const float4*)(feats + ((size_t)b * 128) * 16384 + (size_t)h * 128) + lane;

    ull accA[6], accB[6];
#pragma unroll
    for (int jj = 0; jj < 6; jj++) { accA[jj] = 0ull; accB[jj] = 0ull; }
    ull f2xy = 0ull, f2zw = 0ull;

#pragma unroll 4
    for (int c = 0; c < 128; c++) {
        float4 f = fp[(size_t)c * 4096];
        ull fxy = pack2(f.x, f.y);
        ull fzw = pack2(f.z, f.w);
        f2xy = ffma2(fxy, fxy, f2xy);
        f2zw = ffma2(fzw, fzw, f2zw);
#pragma unroll
        for (int jj = 0; jj < 6; jj++) {
            ull pv = spr2[(j0 + jj) * 128 + c];
            accA[jj] = ffma2(pv, fxy, accA[jj]);
            accB[jj] = ffma2(pv, fzw, accB[jj]);
        }
    }

    float2 f2a = unpk2(f2xy), f2b = unpk2(f2zw);
    int w0 = lane * 4;
#pragma unroll
    for (int jj = 0; jj < 6; jj++) {
        int j = j0 + jj;
        float p2v = sp2[j];
        float2 da = unpk2(accA[jj]), db = unpk2(accB[jj]);
        float4 d;
        d.x = sqrtf(fmaxf(f2a.x + p2v - 2.0f * da.x, 0.0f));
        d.y = sqrtf(fmaxf(f2a.y + p2v - 2.0f * da.y, 0.0f));
        d.z = sqrtf(fmaxf(f2b.x + p2v - 2.0f * db.x, 0.0f));
        d.w = sqrtf(fmaxf(f2b.y + p2v - 2.0f * db.y, 0.0f));
        size_t o = ((size_t)(b * 48 + j) << 14) + (size_t)(h * 128 + w0);
        *reinterpret_cast<float4*>(out_dist + o) = d;
        float4 xv;
        xv.x = 1.0f / (1.0f + 2.0f * d.x);
        xv.y = 1.0f / (1.0f + 2.0f * d.y);
        xv.z = 1.0f / (1.0f + 2.0f * d.z);
        xv.w = 1.0f / (1.0f + 2.0f * d.w);
        ((float4*)sd)[j * 32 + lane] = xv;
    }
    __syncthreads();

    {
        int w = tid >> 1;
        int half = tid & 1;
        int jb = half * 24;
        float xv[24];
        float s = 0;
#pragma unroll
        for (int t = 0; t < 24; t++) {
            xv[t] = sd[(jb + t) * 128 + w];
            s += xv[t];
        }
        s += __shfl_xor_sync(0xffffffffu, s, 1);
        float mu = s * (1.0f / 48.0f);
        float vs = 0;
#pragma unroll
        for (int t = 0; t < 24; t++) { float d = xv[t] - mu; vs += d * d; }
        vs += __shfl_xor_sync(0xffffffffu, vs, 1);
        float inv = 1.0f / sqrtf(vs * (1.0f / 48.0f) + 1e-6f);

        float mx[6];
#pragma unroll
        for (int ncc = 0; ncc < 6; ncc++) mx[ncc] = -3.4e38f;
        size_t ob = ((size_t)(b * 48) << 14) + (size_t)(h * 128 + w);
#pragma unroll
        for (int t = 0; t < 24; t++) {
            int j = jb + t;
            float y = (xv[t] - mu) * inv * sg2[j] + sb2[j];
            float gv = gelu_exact(y);
            out_p2c[ob + ((size_t)j << 14)] = gv;
            int ncc = t % 6;
            mx[ncc] = fmaxf(mx[ncc], gv);
        }
#pragma unroll
        for (int ncc = 0; ncc < 6; ncc++)
            mx[ncc] = fmaxf(mx[ncc], __shfl_xor_sync(0xffffffffu, mx[ncc], 1));
        if (half == 0) {
            size_t pb = ((size_t)(b * 6) << 14) + (size_t)(h * 128 + w);
#pragma unroll
            for (int ncc = 0; ncc < 6; ncc++)
                g_pred[pb + ((size_t)ncc << 14)] = mx[ncc];
        }
    }
}

// ============================================================
// K4: bilinear 128->512 (jax half-pixel centers, edge clamp)
// ============================================================
__global__ void k4_resize(float* __restrict__ out_pred) {
    int idx = blockIdx.x * blockDim.x + threadIdx.x;
    int ox = idx & 511;
    int oy = (idx >> 9) & 511;
    int ch = idx >> 18;
    const float* src = g_pred + ((size_t)ch << 14);
    float sx = (ox + 0.5f) * 0.25f - 0.5f;
    float sy = (oy + 0.5f) * 0.25f - 0.5f;
    float x0f = floorf(sx), y0f = floorf(sy);
    float fx = sx - x0f, fy = sy - y0f;
    int x0 = (int)x0f, y0 = (int)y0f;
    int x0c = max(x0, 0), x1c = min(x0 + 1, 127);
    int y0c = max(y0, 0), y1c = min(y0 + 1, 127);
    float v00 = src[y0c * 128 + x0c], v01 = src[y0c * 128 + x1c];
    float v10 = src[y1c * 128 + x0c], v11 = src[y1c * 128 + x1c];
    float top = v00 + fx * (v01 - v00);
    float bot = v10 + fx * (v11 - v10);
    out_pred[idx] = top + fy * (bot - top);
}

extern "C" void kernel_launch(void* const* d_in, const int* in_sizes, int n_in,
                              void* d_out, int out_size) {
    const float* feats       = (const float*)d_in[0];
    const int*   gt32        = (const int*)d_in[1];
    const float* prototype   = (const float*)d_in[2];
    const float* ln1g        = (const float*)d_in[3];
    const float* ln1b        = (const float*)d_in[4];
    const float* ln2g        = (const float*)d_in[5];
    const float* ln2b        = (const float*)d_in[6];

    float* out = (float*)d_out;
    float* out_pred = out;                    // 12582912
    float* out_pexp = out + 12582912;         // 49152
    float* out_p2c  = out + 12632064;         // 6291456
    float* out_dist = out + 18923520;         // 6291456
    float* out_pnew = out + 25214976;         // 6144

    cudaFuncSetAttribute(k3_dist, cudaFuncAttributeMaxDynamicSharedMemorySize, 18576 * 4);

    k0_emap<<<512, 256>>>(gt32);
    dim3 g1(128, 4);
    k1b_sums<<<g1, 256>>>(feats);
    k1c_centers<<<128, 192>>>(prototype, ln1g, ln1b);
    k2_proto<<<48, 512>>>(prototype, out_pnew, out_pexp);
    dim3 g3(128, 8);
    k3_dist<<<g3, 256, 18576 * 4>>>(feats, ln2g, ln2b, out_p2c, out_dist);
    k4_resize<<<49152, 256>>>(out_pred);
}